// round 8
// baseline (speedup 1.0000x reference)
#include <cuda_runtime.h>
#include <cuda_fp16.h>

#define NN 50000
#define NE 800000
#define NBLK ((NN + 255) / 256)   // 196 scan blocks

// ---------------- scratch (static device globals — no allocation) ----------------
__device__ __half g_h0h[NN * 128];   // layer0 features h = x@W0, fp16 for gather
__device__ float  g_as0[NN * 8];     // per (node, head) src projection
__device__ float  g_ad0[NN * 8];
__device__ float  g_e0[NE * 8];      // per-edge ex values, CSR order
__device__ float  g_acc0[NN * 128];  // layer0 output (post-ELU), fp32
__device__ float  g_h1[NN * 40];
__device__ float  g_as1[NN];
__device__ float  g_ad1[NN];
__device__ float  g_e1[NE];
__device__ int    g_src[NE];         // original order
__device__ int    g_dst[NE];
__device__ int    g_csrc[NE];        // src sorted by dst (CSR payload)
__device__ int    g_cnt[NN];         // degree
__device__ int    g_off[NN];         // CSR row offsets
__device__ int    g_cur[NN];         // scatter cursors
__device__ int    g_bsum[256];
__device__ int    g_boff[256];
__device__ int    g_is64;

// ---------------- init: zero counters + dtype probe (fused) ----------------
// Sample the first 256 entries interpreted as int64. If all are valid node ids,
// the buffer is int64; under int32 the reinterpreted pairs are astronomically
// out of range (false-positive prob ~ (5e4/2^32)^256 ~ 0).
__global__ void init_kernel(const long long* __restrict__ p) {
    int i = blockIdx.x * blockDim.x + threadIdx.x;
    if (i < NN) { g_cnt[i] = 0; g_cur[i] = 0; }
    if (blockIdx.x == 0) {
        __shared__ int bad;
        if (threadIdx.x == 0) bad = 0;
        __syncthreads();
        long long v = p[threadIdx.x];
        if (v < 0 || v >= NN) atomicOr(&bad, 1);
        __syncthreads();
        if (threadIdx.x == 0) g_is64 = bad ? 0 : 1;
    }
}

__global__ void convert_hist_kernel(const void* __restrict__ ei) {
    int e = blockIdx.x * blockDim.x + threadIdx.x;   // exactly NE threads
    int s, d;
    if (g_is64) {
        const long long* p = (const long long*)ei;
        s = (int)p[e]; d = (int)p[NE + e];
    } else {
        const int* p = (const int*)ei;
        s = p[e]; d = p[NE + e];
    }
    g_src[e] = s; g_dst[e] = d;
    atomicAdd(&g_cnt[d], 1);
}

// ---------------- block scan (3 kernels) ----------------

__global__ void scan1_kernel() {        // grid NBLK, 256 thr: block sums
    __shared__ int sm[256];
    int i = blockIdx.x * 256 + threadIdx.x;
    sm[threadIdx.x] = (i < NN) ? g_cnt[i] : 0;
    __syncthreads();
    for (int o = 128; o > 0; o >>= 1) {
        if (threadIdx.x < o) sm[threadIdx.x] += sm[threadIdx.x + o];
        __syncthreads();
    }
    if (threadIdx.x == 0) g_bsum[blockIdx.x] = sm[0];
}

__global__ void scan2_kernel() {        // 1 block: exclusive scan of block sums
    __shared__ int sm[256];
    int t = threadIdx.x;
    int v = (t < NBLK) ? g_bsum[t] : 0;
    sm[t] = v; __syncthreads();
    for (int o = 1; o < 256; o <<= 1) {
        int a = (t >= o) ? sm[t - o] : 0;
        __syncthreads();
        sm[t] += a;
        __syncthreads();
    }
    g_boff[t] = sm[t] - v;
}

__global__ void scan3_kernel() {        // grid NBLK: in-block exclusive scan + offset
    __shared__ int sm[256];
    int t = threadIdx.x;
    int i = blockIdx.x * 256 + t;
    int v = (i < NN) ? g_cnt[i] : 0;
    sm[t] = v; __syncthreads();
    for (int o = 1; o < 256; o <<= 1) {
        int a = (t >= o) ? sm[t - o] : 0;
        __syncthreads();
        sm[t] += a;
        __syncthreads();
    }
    if (i < NN) g_off[i] = sm[t] - v + g_boff[blockIdx.x];
}

__global__ void scatter_kernel() {
    int e = blockIdx.x * blockDim.x + threadIdx.x;   // exactly NE threads
    int d = g_dst[e];
    int pos = g_off[d] + atomicAdd(&g_cur[d], 1);
    g_csrc[pos] = g_src[e];
}

// ---------------- GEMMs ----------------

// h0 = x @ W0 (50000x128 @ 128x128); fused alpha0 projections; h0 stored fp16.
__global__ void gemm0_kernel(const float* __restrict__ x, const float* __restrict__ W,
                             const float* __restrict__ a_s, const float* __restrict__ a_d) {
    __shared__ float xs[16 * 128];
    const int t  = threadIdx.x;        // 128: one output column each
    const int n0 = blockIdx.x * 16;
#pragma unroll
    for (int i = 0; i < 16; i++) xs[i * 128 + t] = x[(n0 + i) * 128 + t];
    __syncthreads();
    float acc[16];
#pragma unroll
    for (int i = 0; i < 16; i++) acc[i] = 0.f;
    for (int k = 0; k < 128; k += 4) {
        float w0 = W[k * 128 + t], w1 = W[(k + 1) * 128 + t];
        float w2 = W[(k + 2) * 128 + t], w3 = W[(k + 3) * 128 + t];
#pragma unroll
        for (int i = 0; i < 16; i++) {
            float4 xv = *(const float4*)&xs[i * 128 + k];   // broadcast LDS128
            acc[i] += xv.x * w0 + xv.y * w1 + xv.z * w2 + xv.w * w3;
        }
    }
    float asv = a_s[t], adv = a_d[t];   // a_s/a_d are [8,16] = 128 floats
#pragma unroll
    for (int i = 0; i < 16; i++) {
        // fp16 store of h0, packed as half2 by even lanes
        float partner = __shfl_down_sync(0xffffffffu, acc[i], 1);
        if ((t & 1) == 0)
            *(__half2*)&g_h0h[(n0 + i) * 128 + t] = __floats2half2_rn(acc[i], partner);
        // alpha projections from fp32 accumulators (width-16 tree reduce)
        float ps = acc[i] * asv, pd = acc[i] * adv;
#pragma unroll
        for (int o = 8; o > 0; o >>= 1) {
            ps += __shfl_down_sync(0xffffffffu, ps, o, 16);
            pd += __shfl_down_sync(0xffffffffu, pd, o, 16);
        }
        if ((t & 15) == 0) {
            g_as0[(n0 + i) * 8 + (t >> 4)] = ps;
            g_ad0[(n0 + i) * 8 + (t >> 4)] = pd;
        }
    }
}

// h1 = elu_out @ W1 (50000x128 @ 128x40), with alpha1 projections fused via smem.
__global__ void gemm1_kernel(const float* __restrict__ W1,
                             const float* __restrict__ a_s, const float* __restrict__ a_d) {
    __shared__ float xs[40 * 128];
    __shared__ float ws[128 * 40];
    __shared__ float sas[40], sad[40];
    const int t  = threadIdx.x;        // 160
    const int n0 = blockIdx.x * 40;
    for (int i = t; i < 40 * 128; i += 160) xs[i] = g_acc0[n0 * 128 + i];
    for (int i = t; i < 128 * 40; i += 160) ws[i] = W1[i];
    if (t < 40) { sas[t] = 0.f; sad[t] = 0.f; }
    __syncthreads();
    const int c = t % 40, ns = t / 40;
    float acc[10];
#pragma unroll
    for (int j = 0; j < 10; j++) acc[j] = 0.f;
    for (int k = 0; k < 128; k += 4) {
        float w0 = ws[k * 40 + c], w1 = ws[(k + 1) * 40 + c];
        float w2 = ws[(k + 2) * 40 + c], w3 = ws[(k + 3) * 40 + c];
#pragma unroll
        for (int j = 0; j < 10; j++) {
            float4 xv = *(const float4*)&xs[(ns + 4 * j) * 128 + k];
            acc[j] += xv.x * w0 + xv.y * w1 + xv.z * w2 + xv.w * w3;
        }
    }
    float avs = a_s[c], avd = a_d[c];
#pragma unroll
    for (int j = 0; j < 10; j++) {
        int node = ns + 4 * j;                     // local node index 0..39
        g_h1[(n0 + node) * 40 + c] = acc[j];
        atomicAdd(&sas[node], acc[j] * avs);
        atomicAdd(&sad[node], acc[j] * avd);
    }
    __syncthreads();
    if (t < 40) { g_as1[n0 + t] = sas[t]; g_ad1[n0 + t] = sad[t]; }
}

// ---------------- fused per-node softmax + aggregation ----------------
// Softmax without max-subtraction (logits are O(1) here; identical result).

// layer0: one warp per node. 8 heads x 16 dims; h0 gathered in fp16.
__global__ void node_l0_kernel(const float* __restrict__ b0) {
    int n = blockIdx.x * (blockDim.x >> 5) + (threadIdx.x >> 5);
    if (n >= NN) return;
    int lane = threadIdx.x & 31;
    int off = g_off[n], deg = g_cnt[n];

    float ad[8];
#pragma unroll
    for (int h = 0; h < 8; h++) ad[h] = g_ad0[n * 8 + h];   // broadcast

    float den[8] = {0.f, 0.f, 0.f, 0.f, 0.f, 0.f, 0.f, 0.f};
    for (int j = lane; j < deg; j += 32) {
        int s = g_csrc[off + j];
#pragma unroll
        for (int h = 0; h < 8; h++) {
            float v = g_as0[s * 8 + h] + ad[h];
            v = v > 0.f ? v : 0.2f * v;
            float ex = __expf(v);
            g_e0[(off + j) * 8 + h] = ex;
            den[h] += ex;
        }
    }
#pragma unroll
    for (int h = 0; h < 8; h++) {
        float v = den[h];
#pragma unroll
        for (int o = 16; o > 0; o >>= 1) v += __shfl_xor_sync(0xffffffffu, v, o);
        den[h] = 1.f / (v + 1e-16f);
    }

    int h = lane >> 2, f = lane << 2;
    float inv = (h == 0) ? den[0] : (h == 1) ? den[1] : (h == 2) ? den[2] :
                (h == 3) ? den[3] : (h == 4) ? den[4] : (h == 5) ? den[5] :
                (h == 6) ? den[6] : den[7];

    float4 acc = make_float4(0.f, 0.f, 0.f, 0.f);
#pragma unroll 4
    for (int j = 0; j < deg; j++) {
        int s = g_csrc[off + j];                        // broadcast
        float a = g_e0[(off + j) * 8 + h] * inv;
        uint2 u = *(const uint2*)&g_h0h[s * 128 + f];   // 8B/lane, 256B/warp coalesced
        __half2 p0 = *(__half2*)&u.x, p1 = *(__half2*)&u.y;
        float2 f0 = __half22float2(p0), f1 = __half22float2(p1);
        acc.x += f0.x * a; acc.y += f0.y * a;
        acc.z += f1.x * a; acc.w += f1.y * a;
    }
    float4 bb = *(const float4*)&b0[f];
    acc.x += bb.x; acc.y += bb.y; acc.z += bb.z; acc.w += bb.w;
    acc.x = acc.x > 0.f ? acc.x : expm1f(acc.x);
    acc.y = acc.y > 0.f ? acc.y : expm1f(acc.y);
    acc.z = acc.z > 0.f ? acc.z : expm1f(acc.z);
    acc.w = acc.w > 0.f ? acc.w : expm1f(acc.w);
    *(float4*)&g_acc0[n * 128 + f] = acc;
}

// layer1: one warp per node. 1 head x 40 dims (lanes 0..9 carry float4 acc).
__global__ void node_l1_kernel(float* __restrict__ out, const float* __restrict__ b1) {
    int n = blockIdx.x * (blockDim.x >> 5) + (threadIdx.x >> 5);
    if (n >= NN) return;
    int lane = threadIdx.x & 31;
    int off = g_off[n], deg = g_cnt[n];

    float adv = g_ad1[n];
    float den = 0.f;
    for (int j = lane; j < deg; j += 32) {
        int s = g_csrc[off + j];
        float v = g_as1[s] + adv;
        v = v > 0.f ? v : 0.2f * v;
        float ex = __expf(v);
        g_e1[off + j] = ex;
        den += ex;
    }
#pragma unroll
    for (int o = 16; o > 0; o >>= 1) den += __shfl_xor_sync(0xffffffffu, den, o);
    float inv = 1.f / (den + 1e-16f);

    int f = lane << 2;
    float4 acc = make_float4(0.f, 0.f, 0.f, 0.f);
#pragma unroll 4
    for (int j = 0; j < deg; j++) {
        int s = g_csrc[off + j];                 // broadcast
        float a = g_e1[off + j] * inv;           // broadcast
        if (lane < 10) {
            float4 hv = *(const float4*)&g_h1[s * 40 + f];
            acc.x += hv.x * a; acc.y += hv.y * a;
            acc.z += hv.z * a; acc.w += hv.w * a;
        }
    }
    if (lane < 10) {
        float4 bb = *(const float4*)&b1[f];
        acc.x += bb.x; acc.y += bb.y; acc.z += bb.z; acc.w += bb.w;
        *(float4*)&out[n * 40 + f] = acc;
    }
}

// ---------------- launcher ----------------
extern "C" void kernel_launch(void* const* d_in, const int* in_sizes, int n_in,
                              void* d_out, int out_size) {
    const float* x     = (const float*)d_in[0];
    const void*  ei    = d_in[1];                  // int32 or int64 — detected on device
    const float* W0    = (const float*)d_in[2];
    const float* av_s0 = (const float*)d_in[3];
    const float* av_d0 = (const float*)d_in[4];
    const float* b0    = (const float*)d_in[5];
    const float* W1    = (const float*)d_in[6];
    const float* av_s1 = (const float*)d_in[7];
    const float* av_d1 = (const float*)d_in[8];
    const float* b1    = (const float*)d_in[9];
    float* out = (float*)d_out;

    const int TB = 256;

    // ---- CSR build (shared by both layers) ----
    init_kernel<<<NBLK, TB>>>((const long long*)ei);
    convert_hist_kernel<<<NE / TB, TB>>>(ei);
    scan1_kernel<<<NBLK, TB>>>();
    scan2_kernel<<<1, TB>>>();
    scan3_kernel<<<NBLK, TB>>>();
    scatter_kernel<<<NE / TB, TB>>>();

    // ---- layer 0 ----
    gemm0_kernel<<<NN / 16, 128>>>(x, W0, av_s0, av_d0);
    node_l0_kernel<<<(NN + 7) / 8, 256>>>(b0);

    // ---- layer 1 ----
    gemm1_kernel<<<NN / 40, 160>>>(W1, av_s1, av_d1);
    node_l1_kernel<<<(NN + 7) / 8, 256>>>(out, b1);
}

// round 9
// speedup vs baseline: 1.2667x; 1.2667x over previous
#include <cuda_runtime.h>

#define NN 50000
#define NE 800000
#define NBLK ((NN + 255) / 256)   // 196 scan blocks

// ---------------- scratch (static device globals — no allocation) ----------------
__device__ float g_h0[NN * 128];     // layer0 features h = x@W0
__device__ float g_as0[NN * 8];      // per (node, head) src projection
__device__ float g_ad0[NN * 8];
__device__ float g_acc0[NN * 128];   // layer0 output (post-ELU)
__device__ float g_h1[NN * 40];
__device__ float g_as1[NN];
__device__ float g_ad1[NN];
__device__ int   g_src[NE];          // original order
__device__ int   g_dst[NE];
__device__ int   g_csrc[NE];         // src sorted by dst (CSR payload)
__device__ int   g_cnt[NN];          // degree
__device__ int   g_off[NN];          // CSR row offsets
__device__ int   g_cur[NN];          // scatter cursors
__device__ int   g_bsum[256];
__device__ int   g_boff[256];
__device__ int   g_is64;

// ---------------- init: zero counters + dtype probe (fused) ----------------
__global__ void init_kernel(const long long* __restrict__ p) {
    int i = blockIdx.x * blockDim.x + threadIdx.x;
    if (i < NN) { g_cnt[i] = 0; g_cur[i] = 0; }
    if (blockIdx.x == 0) {
        __shared__ int bad;
        if (threadIdx.x == 0) bad = 0;
        __syncthreads();
        long long v = p[threadIdx.x];
        if (v < 0 || v >= NN) atomicOr(&bad, 1);
        __syncthreads();
        if (threadIdx.x == 0) g_is64 = bad ? 0 : 1;
    }
}

__global__ void convert_hist_kernel(const void* __restrict__ ei) {
    int e = blockIdx.x * blockDim.x + threadIdx.x;   // exactly NE threads
    int s, d;
    if (g_is64) {
        const long long* p = (const long long*)ei;
        s = (int)p[e]; d = (int)p[NE + e];
    } else {
        const int* p = (const int*)ei;
        s = p[e]; d = p[NE + e];
    }
    g_src[e] = s; g_dst[e] = d;
    atomicAdd(&g_cnt[d], 1);
}

// ---------------- block scan (3 kernels) ----------------

__global__ void scan1_kernel() {
    __shared__ int sm[256];
    int i = blockIdx.x * 256 + threadIdx.x;
    sm[threadIdx.x] = (i < NN) ? g_cnt[i] : 0;
    __syncthreads();
    for (int o = 128; o > 0; o >>= 1) {
        if (threadIdx.x < o) sm[threadIdx.x] += sm[threadIdx.x + o];
        __syncthreads();
    }
    if (threadIdx.x == 0) g_bsum[blockIdx.x] = sm[0];
}

__global__ void scan2_kernel() {
    __shared__ int sm[256];
    int t = threadIdx.x;
    int v = (t < NBLK) ? g_bsum[t] : 0;
    sm[t] = v; __syncthreads();
    for (int o = 1; o < 256; o <<= 1) {
        int a = (t >= o) ? sm[t - o] : 0;
        __syncthreads();
        sm[t] += a;
        __syncthreads();
    }
    g_boff[t] = sm[t] - v;
}

__global__ void scan3_kernel() {
    __shared__ int sm[256];
    int t = threadIdx.x;
    int i = blockIdx.x * 256 + t;
    int v = (i < NN) ? g_cnt[i] : 0;
    sm[t] = v; __syncthreads();
    for (int o = 1; o < 256; o <<= 1) {
        int a = (t >= o) ? sm[t - o] : 0;
        __syncthreads();
        sm[t] += a;
        __syncthreads();
    }
    if (i < NN) g_off[i] = sm[t] - v + g_boff[blockIdx.x];
}

__global__ void scatter_kernel() {
    int e = blockIdx.x * blockDim.x + threadIdx.x;   // exactly NE threads
    int d = g_dst[e];
    int pos = g_off[d] + atomicAdd(&g_cur[d], 1);
    g_csrc[pos] = g_src[e];
}

// ---------------- GEMMs ----------------

// h0 = x @ W0 (50000x128 @ 128x128); fused alpha0 projections.
__global__ void gemm0_kernel(const float* __restrict__ x, const float* __restrict__ W,
                             const float* __restrict__ a_s, const float* __restrict__ a_d) {
    __shared__ float xs[16 * 128];
    const int t  = threadIdx.x;        // 128: one output column each
    const int n0 = blockIdx.x * 16;
#pragma unroll
    for (int i = 0; i < 16; i++) xs[i * 128 + t] = x[(n0 + i) * 128 + t];
    __syncthreads();
    float acc[16];
#pragma unroll
    for (int i = 0; i < 16; i++) acc[i] = 0.f;
    for (int k = 0; k < 128; k += 4) {
        float w0 = W[k * 128 + t], w1 = W[(k + 1) * 128 + t];
        float w2 = W[(k + 2) * 128 + t], w3 = W[(k + 3) * 128 + t];
#pragma unroll
        for (int i = 0; i < 16; i++) {
            float4 xv = *(const float4*)&xs[i * 128 + k];   // broadcast LDS128
            acc[i] += xv.x * w0 + xv.y * w1 + xv.z * w2 + xv.w * w3;
        }
    }
    float asv = a_s[t], adv = a_d[t];   // a_s/a_d are [8,16] = 128 floats
#pragma unroll
    for (int i = 0; i < 16; i++) {
        g_h0[(n0 + i) * 128 + t] = acc[i];
        float ps = acc[i] * asv, pd = acc[i] * adv;
#pragma unroll
        for (int o = 8; o > 0; o >>= 1) {
            ps += __shfl_down_sync(0xffffffffu, ps, o, 16);
            pd += __shfl_down_sync(0xffffffffu, pd, o, 16);
        }
        if ((t & 15) == 0) {
            g_as0[(n0 + i) * 8 + (t >> 4)] = ps;
            g_ad0[(n0 + i) * 8 + (t >> 4)] = pd;
        }
    }
}

// h1 = elu_out @ W1 (50000x128 @ 128x40). 40 nodes/block, 160 threads.
__global__ void gemm1_kernel(const float* __restrict__ W1) {
    __shared__ float xs[40 * 128];
    __shared__ float ws[128 * 40];
    const int t  = threadIdx.x;
    const int n0 = blockIdx.x * 40;
    for (int i = t; i < 40 * 128; i += 160) xs[i] = g_acc0[n0 * 128 + i];
    for (int i = t; i < 128 * 40; i += 160) ws[i] = W1[i];
    __syncthreads();
    const int c = t % 40, ns = t / 40;
    float acc[10];
#pragma unroll
    for (int j = 0; j < 10; j++) acc[j] = 0.f;
    for (int k = 0; k < 128; k += 4) {
        float w0 = ws[k * 40 + c], w1 = ws[(k + 1) * 40 + c];
        float w2 = ws[(k + 2) * 40 + c], w3 = ws[(k + 3) * 40 + c];
#pragma unroll
        for (int j = 0; j < 10; j++) {
            float4 xv = *(const float4*)&xs[(ns + 4 * j) * 128 + k];
            acc[j] += xv.x * w0 + xv.y * w1 + xv.z * w2 + xv.w * w3;
        }
    }
#pragma unroll
    for (int j = 0; j < 10; j++) g_h1[(n0 + ns + 4 * j) * 40 + c] = acc[j];
}

__global__ void alpha1_kernel(const float* __restrict__ a_s, const float* __restrict__ a_d) {
    int n = blockIdx.x * blockDim.x + threadIdx.x;
    if (n >= NN) return;
    const float* hp = &g_h1[n * 40];
    float s = 0.f, d = 0.f;
#pragma unroll
    for (int j = 0; j < 40; j++) {
        float v = hp[j];
        s += v * a_s[j];
        d += v * a_d[j];
    }
    g_as1[n] = s; g_ad1[n] = d;
}

// ---------------- fused per-node softmax + aggregation ----------------
// Softmax without max-subtraction (logits are O(1) here; identical result).
// No per-edge ex scratch: pass A computes denominators only; pass B recomputes
// exp(lrelu(.)) — the as0 reload costs the same bytes the ex reload would have.

__device__ __forceinline__ float lrelu_exp(float v) {
    v = v > 0.f ? v : 0.2f * v;
    return __expf(v);
}

// layer0: one warp per node. 8 heads x 16 dims.
__global__ void node_l0_kernel(const float* __restrict__ b0) {
    int n = blockIdx.x * (blockDim.x >> 5) + (threadIdx.x >> 5);
    if (n >= NN) return;
    int lane = threadIdx.x & 31;
    int off = g_off[n], deg = g_cnt[n];

    float ad[8];
#pragma unroll
    for (int h = 0; h < 8; h++) ad[h] = g_ad0[n * 8 + h];   // broadcast

    // pass A: denominators (register accumulation, warp reduce)
    float den[8] = {0.f, 0.f, 0.f, 0.f, 0.f, 0.f, 0.f, 0.f};
    for (int j = lane; j < deg; j += 32) {
        int s = g_csrc[off + j];
        float4 a0 = *(const float4*)&g_as0[s * 8];
        float4 a1 = *(const float4*)&g_as0[s * 8 + 4];
        den[0] += lrelu_exp(a0.x + ad[0]);
        den[1] += lrelu_exp(a0.y + ad[1]);
        den[2] += lrelu_exp(a0.z + ad[2]);
        den[3] += lrelu_exp(a0.w + ad[3]);
        den[4] += lrelu_exp(a1.x + ad[4]);
        den[5] += lrelu_exp(a1.y + ad[5]);
        den[6] += lrelu_exp(a1.z + ad[6]);
        den[7] += lrelu_exp(a1.w + ad[7]);
    }
#pragma unroll
    for (int h = 0; h < 8; h++) {
        float v = den[h];
#pragma unroll
        for (int o = 16; o > 0; o >>= 1) v += __shfl_xor_sync(0xffffffffu, v, o);
        den[h] = 1.f / (v + 1e-16f);
    }

    int h = lane >> 2, f = lane << 2;
    float inv = (h == 0) ? den[0] : (h == 1) ? den[1] : (h == 2) ? den[2] :
                (h == 3) ? den[3] : (h == 4) ? den[4] : (h == 5) ? den[5] :
                (h == 6) ? den[6] : den[7];
    float adh = (h == 0) ? ad[0] : (h == 1) ? ad[1] : (h == 2) ? ad[2] :
                (h == 3) ? ad[3] : (h == 4) ? ad[4] : (h == 5) ? ad[5] :
                (h == 6) ? ad[6] : ad[7];

    // pass B: aggregation, hand-unrolled x4 for memory-level parallelism
    float4 acc = make_float4(0.f, 0.f, 0.f, 0.f);
    int j = 0;
    for (; j + 4 <= deg; j += 4) {
        int s0 = g_csrc[off + j],     s1 = g_csrc[off + j + 1];
        int s2 = g_csrc[off + j + 2], s3 = g_csrc[off + j + 3];
        float q0 = g_as0[s0 * 8 + h], q1 = g_as0[s1 * 8 + h];
        float q2 = g_as0[s2 * 8 + h], q3 = g_as0[s3 * 8 + h];
        float4 v0 = *(const float4*)&g_h0[s0 * 128 + f];
        float4 v1 = *(const float4*)&g_h0[s1 * 128 + f];
        float4 v2 = *(const float4*)&g_h0[s2 * 128 + f];
        float4 v3 = *(const float4*)&g_h0[s3 * 128 + f];
        float a0 = lrelu_exp(q0 + adh) * inv;
        float a1 = lrelu_exp(q1 + adh) * inv;
        float a2 = lrelu_exp(q2 + adh) * inv;
        float a3 = lrelu_exp(q3 + adh) * inv;
        acc.x += v0.x * a0 + v1.x * a1 + v2.x * a2 + v3.x * a3;
        acc.y += v0.y * a0 + v1.y * a1 + v2.y * a2 + v3.y * a3;
        acc.z += v0.z * a0 + v1.z * a1 + v2.z * a2 + v3.z * a3;
        acc.w += v0.w * a0 + v1.w * a1 + v2.w * a2 + v3.w * a3;
    }
    for (; j < deg; j++) {
        int s = g_csrc[off + j];
        float a = lrelu_exp(g_as0[s * 8 + h] + adh) * inv;
        float4 hv = *(const float4*)&g_h0[s * 128 + f];
        acc.x += hv.x * a; acc.y += hv.y * a;
        acc.z += hv.z * a; acc.w += hv.w * a;
    }
    float4 bb = *(const float4*)&b0[f];
    acc.x += bb.x; acc.y += bb.y; acc.z += bb.z; acc.w += bb.w;
    acc.x = acc.x > 0.f ? acc.x : expm1f(acc.x);
    acc.y = acc.y > 0.f ? acc.y : expm1f(acc.y);
    acc.z = acc.z > 0.f ? acc.z : expm1f(acc.z);
    acc.w = acc.w > 0.f ? acc.w : expm1f(acc.w);
    *(float4*)&g_acc0[n * 128 + f] = acc;
}

// layer1: one warp per node. 1 head x 40 dims (lanes 0..9 carry float4 acc).
__global__ void node_l1_kernel(float* __restrict__ out, const float* __restrict__ b1) {
    int n = blockIdx.x * (blockDim.x >> 5) + (threadIdx.x >> 5);
    if (n >= NN) return;
    int lane = threadIdx.x & 31;
    int off = g_off[n], deg = g_cnt[n];

    float adv = g_ad1[n];
    float den = 0.f;
    for (int j = lane; j < deg; j += 32) {
        int s = g_csrc[off + j];
        den += lrelu_exp(g_as1[s] + adv);
    }
#pragma unroll
    for (int o = 16; o > 0; o >>= 1) den += __shfl_xor_sync(0xffffffffu, den, o);
    float inv = 1.f / (den + 1e-16f);

    int f = lane << 2;
    bool act = lane < 10;
    float4 acc = make_float4(0.f, 0.f, 0.f, 0.f);
    int j = 0;
    for (; j + 4 <= deg; j += 4) {
        int s0 = g_csrc[off + j],     s1 = g_csrc[off + j + 1];
        int s2 = g_csrc[off + j + 2], s3 = g_csrc[off + j + 3];
        float q0 = g_as1[s0], q1 = g_as1[s1], q2 = g_as1[s2], q3 = g_as1[s3];
        if (act) {
            float4 v0 = *(const float4*)&g_h1[s0 * 40 + f];
            float4 v1 = *(const float4*)&g_h1[s1 * 40 + f];
            float4 v2 = *(const float4*)&g_h1[s2 * 40 + f];
            float4 v3 = *(const float4*)&g_h1[s3 * 40 + f];
            float a0 = lrelu_exp(q0 + adv) * inv;
            float a1 = lrelu_exp(q1 + adv) * inv;
            float a2 = lrelu_exp(q2 + adv) * inv;
            float a3 = lrelu_exp(q3 + adv) * inv;
            acc.x += v0.x * a0 + v1.x * a1 + v2.x * a2 + v3.x * a3;
            acc.y += v0.y * a0 + v1.y * a1 + v2.y * a2 + v3.y * a3;
            acc.z += v0.z * a0 + v1.z * a1 + v2.z * a2 + v3.z * a3;
            acc.w += v0.w * a0 + v1.w * a1 + v2.w * a2 + v3.w * a3;
        }
    }
    for (; j < deg; j++) {
        int s = g_csrc[off + j];
        if (act) {
            float a = lrelu_exp(g_as1[s] + adv) * inv;
            float4 hv = *(const float4*)&g_h1[s * 40 + f];
            acc.x += hv.x * a; acc.y += hv.y * a;
            acc.z += hv.z * a; acc.w += hv.w * a;
        }
    }
    if (act) {
        float4 bb = *(const float4*)&b1[f];
        acc.x += bb.x; acc.y += bb.y; acc.z += bb.z; acc.w += bb.w;
        *(float4*)&out[n * 40 + f] = acc;
    }
}

// ---------------- launcher ----------------
extern "C" void kernel_launch(void* const* d_in, const int* in_sizes, int n_in,
                              void* d_out, int out_size) {
    const float* x     = (const float*)d_in[0];
    const void*  ei    = d_in[1];                  // int32 or int64 — detected on device
    const float* W0    = (const float*)d_in[2];
    const float* av_s0 = (const float*)d_in[3];
    const float* av_d0 = (const float*)d_in[4];
    const float* b0    = (const float*)d_in[5];
    const float* W1    = (const float*)d_in[6];
    const float* av_s1 = (const float*)d_in[7];
    const float* av_d1 = (const float*)d_in[8];
    const float* b1    = (const float*)d_in[9];
    float* out = (float*)d_out;

    const int TB = 256;

    // ---- CSR build (shared by both layers) ----
    init_kernel<<<NBLK, TB>>>((const long long*)ei);
    convert_hist_kernel<<<NE / TB, TB>>>(ei);
    scan1_kernel<<<NBLK, TB>>>();
    scan2_kernel<<<1, TB>>>();
    scan3_kernel<<<NBLK, TB>>>();
    scatter_kernel<<<NE / TB, TB>>>();

    // ---- layer 0 ----
    gemm0_kernel<<<NN / 16, 128>>>(x, W0, av_s0, av_d0);
    node_l0_kernel<<<(NN + 7) / 8, 256>>>(b0);

    // ---- layer 1 ----
    gemm1_kernel<<<NN / 40, 160>>>(W1);
    alpha1_kernel<<<(NN + TB - 1) / TB, TB>>>(av_s1, av_d1);
    node_l1_kernel<<<(NN + 7) / 8, 256>>>(out, b1);
}

// round 10
// speedup vs baseline: 1.2979x; 1.0246x over previous
#include <cuda_runtime.h>
#include <mma.h>
using namespace nvcuda;

#define NN 50000
#define NE 800000
#define NBLK ((NN + 255) / 256)   // 196 scan blocks

// ---------------- scratch (static device globals — no allocation) ----------------
__device__ float g_h0[NN * 128];     // layer0 features h = x@W0
__device__ float g_as0[NN * 8];      // per (node, head) src projection
__device__ float g_ad0[NN * 8];
__device__ float g_acc0[NN * 128];   // layer0 output (post-ELU)
__device__ float g_h1[NN * 40];
__device__ float g_as1[NN];
__device__ float g_ad1[NN];
__device__ int   g_csrc[NE];         // src sorted by dst (CSR payload)
__device__ int   g_cnt[NN];          // degree
__device__ int   g_off[NN];          // CSR row offsets
__device__ int   g_cur[NN];          // scatter cursors
__device__ int   g_bsum[256];
__device__ int   g_is64;

// ---------------- init: zero counters + dtype probe (fused) ----------------
__global__ void init_kernel(const long long* __restrict__ p) {
    int i = blockIdx.x * blockDim.x + threadIdx.x;
    if (i < NN) { g_cnt[i] = 0; g_cur[i] = 0; }
    if (blockIdx.x == 0) {
        __shared__ int bad;
        if (threadIdx.x == 0) bad = 0;
        __syncthreads();
        long long v = p[threadIdx.x];
        if (v < 0 || v >= NN) atomicOr(&bad, 1);
        __syncthreads();
        if (threadIdx.x == 0) g_is64 = bad ? 0 : 1;
    }
}

// histogram of dst (reads only the dst half of edge_index)
__global__ void hist_kernel(const void* __restrict__ ei) {
    int e = blockIdx.x * blockDim.x + threadIdx.x;   // exactly NE threads
    int d;
    if (g_is64) d = (int)((const long long*)ei)[NE + e];
    else        d = ((const int*)ei)[NE + e];
    atomicAdd(&g_cnt[d], 1);
}

// ---------------- block scan (2 kernels) ----------------

__global__ void scan1_kernel() {
    __shared__ int sm[256];
    int i = blockIdx.x * 256 + threadIdx.x;
    sm[threadIdx.x] = (i < NN) ? g_cnt[i] : 0;
    __syncthreads();
    for (int o = 128; o > 0; o >>= 1) {
        if (threadIdx.x < o) sm[threadIdx.x] += sm[threadIdx.x + o];
        __syncthreads();
    }
    if (threadIdx.x == 0) g_bsum[blockIdx.x] = sm[0];
}

// fused: each block computes its own prefix over g_bsum, then in-block scan
__global__ void scan23_kernel() {
    __shared__ int sm[256];
    __shared__ int boff;
    int t = threadIdx.x;
    int partial = 0;
    for (int i = t; i < blockIdx.x; i += 256) partial += g_bsum[i];
    sm[t] = partial; __syncthreads();
    for (int o = 128; o > 0; o >>= 1) {
        if (t < o) sm[t] += sm[t + o];
        __syncthreads();
    }
    if (t == 0) boff = sm[0];
    __syncthreads();
    int i = blockIdx.x * 256 + t;
    int v = (i < NN) ? g_cnt[i] : 0;
    sm[t] = v; __syncthreads();
    for (int o = 1; o < 256; o <<= 1) {
        int a = (t >= o) ? sm[t - o] : 0;
        __syncthreads();
        sm[t] += a;
        __syncthreads();
    }
    if (i < NN) g_off[i] = sm[t] - v + boff;
}

// scatter reads edge_index directly (no src/dst staging buffers)
__global__ void scatter_kernel(const void* __restrict__ ei) {
    int e = blockIdx.x * blockDim.x + threadIdx.x;   // exactly NE threads
    int s, d;
    if (g_is64) {
        const long long* p = (const long long*)ei;
        s = (int)p[e]; d = (int)p[NE + e];
    } else {
        const int* p = (const int*)ei;
        s = p[e]; d = p[NE + e];
    }
    int pos = g_off[d] + atomicAdd(&g_cur[d], 1);
    g_csrc[pos] = s;
}

// ---------------- GEMMs ----------------

// h0 = x @ W0 via fp16 WMMA (fp32 accumulate). 64 nodes/block, 4 warps.
// alpha0 projections computed from the fp32 C tile in smem.
__global__ void gemm0_wmma_kernel(const float* __restrict__ x, const float* __restrict__ W,
                                  const float* __restrict__ a_s, const float* __restrict__ a_d) {
    __shared__ __align__(16) char buf[49152];
    half*  xs = (half*)buf;                  // 64*128 half = 16KB
    half*  ws = (half*)(buf + 16384);        // 128*128 half = 32KB
    float* cs = (float*)buf;                 // 64*128 float = 32KB (aliases, post-sync)

    const int t    = threadIdx.x;            // 128
    const int warp = t >> 5;
    const int n0   = blockIdx.x * 64;

    for (int i = t; i < 64 * 128; i += 128) {
        int n = n0 + (i >> 7);
        xs[i] = __float2half(n < NN ? x[n * 128 + (i & 127)] : 0.f);
    }
    for (int i = t; i < 128 * 128; i += 128) ws[i] = __float2half(W[i]);
    __syncthreads();

    wmma::fragment<wmma::accumulator, 16, 16, 16, float> c[8];
#pragma unroll
    for (int n = 0; n < 8; n++) wmma::fill_fragment(c[n], 0.f);
#pragma unroll
    for (int k = 0; k < 8; k++) {
        wmma::fragment<wmma::matrix_a, 16, 16, 16, half, wmma::row_major> a;
        wmma::load_matrix_sync(a, xs + warp * 16 * 128 + k * 16, 128);
#pragma unroll
        for (int n = 0; n < 8; n++) {
            wmma::fragment<wmma::matrix_b, 16, 16, 16, half, wmma::row_major> b;
            wmma::load_matrix_sync(b, ws + k * 16 * 128 + n * 16, 128);
            wmma::mma_sync(c[n], a, b, c[n]);
        }
    }
    __syncthreads();   // done reading xs/ws; cs may now overwrite them
#pragma unroll
    for (int n = 0; n < 8; n++)
        wmma::store_matrix_sync(cs + warp * 16 * 128 + n * 16, c[n], 128, wmma::mem_row_major);
    __syncthreads();

    // write h0
    for (int i = t; i < 64 * 128; i += 128) {
        int n = n0 + (i >> 7);
        if (n < NN) g_h0[n * 128 + (i & 127)] = cs[i];
    }
    // alpha projections: 512 (row, head) pairs, 4 per thread
    for (int p = t; p < 512; p += 128) {
        int r = p >> 3, h = p & 7;
        int n = n0 + r;
        if (n < NN) {
            const float* cp = cs + r * 128 + h * 16;
            float s = 0.f, d = 0.f;
#pragma unroll
            for (int j = 0; j < 16; j++) {
                float v = cp[j];
                s += v * a_s[h * 16 + j];
                d += v * a_d[h * 16 + j];
            }
            g_as0[n * 8 + h] = s;
            g_ad0[n * 8 + h] = d;
        }
    }
}

// h1 = elu_out @ W1 (50000x128 @ 128x40). 40 nodes/block, 160 threads.
__global__ void gemm1_kernel(const float* __restrict__ W1) {
    __shared__ float xs[40 * 128];
    __shared__ float ws[128 * 40];
    const int t  = threadIdx.x;
    const int n0 = blockIdx.x * 40;
    for (int i = t; i < 40 * 128; i += 160) xs[i] = g_acc0[n0 * 128 + i];
    for (int i = t; i < 128 * 40; i += 160) ws[i] = W1[i];
    __syncthreads();
    const int c = t % 40, ns = t / 40;
    float acc[10];
#pragma unroll
    for (int j = 0; j < 10; j++) acc[j] = 0.f;
    for (int k = 0; k < 128; k += 4) {
        float w0 = ws[k * 40 + c], w1 = ws[(k + 1) * 40 + c];
        float w2 = ws[(k + 2) * 40 + c], w3 = ws[(k + 3) * 40 + c];
#pragma unroll
        for (int j = 0; j < 10; j++) {
            float4 xv = *(const float4*)&xs[(ns + 4 * j) * 128 + k];
            acc[j] += xv.x * w0 + xv.y * w1 + xv.z * w2 + xv.w * w3;
        }
    }
#pragma unroll
    for (int j = 0; j < 10; j++) g_h1[(n0 + ns + 4 * j) * 40 + c] = acc[j];
}

__global__ void alpha1_kernel(const float* __restrict__ a_s, const float* __restrict__ a_d) {
    int n = blockIdx.x * blockDim.x + threadIdx.x;
    if (n >= NN) return;
    const float* hp = &g_h1[n * 40];
    float s = 0.f, d = 0.f;
#pragma unroll
    for (int j = 0; j < 40; j++) {
        float v = hp[j];
        s += v * a_s[j];
        d += v * a_d[j];
    }
    g_as1[n] = s; g_ad1[n] = d;
}

// ---------------- fused per-node softmax + aggregation ----------------
// Softmax without max-subtraction (logits are O(1) here; identical result).

__device__ __forceinline__ float lrelu_exp(float v) {
    v = v > 0.f ? v : 0.2f * v;
    return __expf(v);
}

// layer0: one warp per node. 8 heads x 16 dims. (unchanged from R9)
__global__ void node_l0_kernel(const float* __restrict__ b0) {
    int n = blockIdx.x * (blockDim.x >> 5) + (threadIdx.x >> 5);
    if (n >= NN) return;
    int lane = threadIdx.x & 31;
    int off = g_off[n], deg = g_cnt[n];

    float ad[8];
#pragma unroll
    for (int h = 0; h < 8; h++) ad[h] = g_ad0[n * 8 + h];

    float den[8] = {0.f, 0.f, 0.f, 0.f, 0.f, 0.f, 0.f, 0.f};
    for (int j = lane; j < deg; j += 32) {
        int s = g_csrc[off + j];
        float4 a0 = *(const float4*)&g_as0[s * 8];
        float4 a1 = *(const float4*)&g_as0[s * 8 + 4];
        den[0] += lrelu_exp(a0.x + ad[0]);
        den[1] += lrelu_exp(a0.y + ad[1]);
        den[2] += lrelu_exp(a0.z + ad[2]);
        den[3] += lrelu_exp(a0.w + ad[3]);
        den[4] += lrelu_exp(a1.x + ad[4]);
        den[5] += lrelu_exp(a1.y + ad[5]);
        den[6] += lrelu_exp(a1.z + ad[6]);
        den[7] += lrelu_exp(a1.w + ad[7]);
    }
#pragma unroll
    for (int h = 0; h < 8; h++) {
        float v = den[h];
#pragma unroll
        for (int o = 16; o > 0; o >>= 1) v += __shfl_xor_sync(0xffffffffu, v, o);
        den[h] = 1.f / (v + 1e-16f);
    }

    int h = lane >> 2, f = lane << 2;
    float inv = (h == 0) ? den[0] : (h == 1) ? den[1] : (h == 2) ? den[2] :
                (h == 3) ? den[3] : (h == 4) ? den[4] : (h == 5) ? den[5] :
                (h == 6) ? den[6] : den[7];
    float adh = (h == 0) ? ad[0] : (h == 1) ? ad[1] : (h == 2) ? ad[2] :
                (h == 3) ? ad[3] : (h == 4) ? ad[4] : (h == 5) ? ad[5] :
                (h == 6) ? ad[6] : ad[7];

    float4 acc = make_float4(0.f, 0.f, 0.f, 0.f);
    int j = 0;
    for (; j + 4 <= deg; j += 4) {
        int s0 = g_csrc[off + j],     s1 = g_csrc[off + j + 1];
        int s2 = g_csrc[off + j + 2], s3 = g_csrc[off + j + 3];
        float q0 = g_as0[s0 * 8 + h], q1 = g_as0[s1 * 8 + h];
        float q2 = g_as0[s2 * 8 + h], q3 = g_as0[s3 * 8 + h];
        float4 v0 = *(const float4*)&g_h0[s0 * 128 + f];
        float4 v1 = *(const float4*)&g_h0[s1 * 128 + f];
        float4 v2 = *(const float4*)&g_h0[s2 * 128 + f];
        float4 v3 = *(const float4*)&g_h0[s3 * 128 + f];
        float a0 = lrelu_exp(q0 + adh) * inv;
        float a1 = lrelu_exp(q1 + adh) * inv;
        float a2 = lrelu_exp(q2 + adh) * inv;
        float a3 = lrelu_exp(q3 + adh) * inv;
        acc.x += v0.x * a0 + v1.x * a1 + v2.x * a2 + v3.x * a3;
        acc.y += v0.y * a0 + v1.y * a1 + v2.y * a2 + v3.y * a3;
        acc.z += v0.z * a0 + v1.z * a1 + v2.z * a2 + v3.z * a3;
        acc.w += v0.w * a0 + v1.w * a1 + v2.w * a2 + v3.w * a3;
    }
    for (; j < deg; j++) {
        int s = g_csrc[off + j];
        float a = lrelu_exp(g_as0[s * 8 + h] + adh) * inv;
        float4 hv = *(const float4*)&g_h0[s * 128 + f];
        acc.x += hv.x * a; acc.y += hv.y * a;
        acc.z += hv.z * a; acc.w += hv.w * a;
    }
    float4 bb = *(const float4*)&b0[f];
    acc.x += bb.x; acc.y += bb.y; acc.z += bb.z; acc.w += bb.w;
    acc.x = acc.x > 0.f ? acc.x : expm1f(acc.x);
    acc.y = acc.y > 0.f ? acc.y : expm1f(acc.y);
    acc.z = acc.z > 0.f ? acc.z : expm1f(acc.z);
    acc.w = acc.w > 0.f ? acc.w : expm1f(acc.w);
    *(float4*)&g_acc0[n * 128 + f] = acc;
}

// layer1: one warp per node; lanes 0-29 split edges 3 ways (10 lanes x 4 feats each).
__global__ void node_l1_kernel(float* __restrict__ out, const float* __restrict__ b1) {
    int n = blockIdx.x * (blockDim.x >> 5) + (threadIdx.x >> 5);
    if (n >= NN) return;
    int lane = threadIdx.x & 31;
    int off = g_off[n], deg = g_cnt[n];

    float adv = g_ad1[n];
    float den = 0.f;
    for (int j = lane; j < deg; j += 32) {
        den += lrelu_exp(g_as1[g_csrc[off + j]] + adv);
    }
#pragma unroll
    for (int o = 16; o > 0; o >>= 1) den += __shfl_xor_sync(0xffffffffu, den, o);
    float inv = 1.f / (den + 1e-16f);

    int grp = lane / 10;           // 0,1,2 active; lane 30,31 -> grp 3 (idle)
    int f   = (lane - grp * 10) << 2;
    float4 acc = make_float4(0.f, 0.f, 0.f, 0.f);
    if (grp < 3) {
        int j = grp;
        for (; j + 4 <= deg; j += 6) {       // handles edges j and j+3
            int s0 = g_csrc[off + j], s1 = g_csrc[off + j + 3];
            float q0 = g_as1[s0], q1 = g_as1[s1];
            float4 v0 = *(const float4*)&g_h1[s0 * 40 + f];
            float4 v1 = *(const float4*)&g_h1[s1 * 40 + f];
            float a0 = lrelu_exp(q0 + adv) * inv;
            float a1 = lrelu_exp(q1 + adv) * inv;
            acc.x += v0.x * a0 + v1.x * a1;
            acc.y += v0.y * a0 + v1.y * a1;
            acc.z += v0.z * a0 + v1.z * a1;
            acc.w += v0.w * a0 + v1.w * a1;
        }
        for (; j < deg; j += 3) {
            int s = g_csrc[off + j];
            float a = lrelu_exp(g_as1[s] + adv) * inv;
            float4 hv = *(const float4*)&g_h1[s * 40 + f];
            acc.x += hv.x * a; acc.y += hv.y * a;
            acc.z += hv.z * a; acc.w += hv.w * a;
        }
    }
    // combine the 3 group partials into lanes 0..9
    float x1 = __shfl_down_sync(0xffffffffu, acc.x, 10);
    float x2 = __shfl_down_sync(0xffffffffu, acc.x, 20);
    float y1 = __shfl_down_sync(0xffffffffu, acc.y, 10);
    float y2 = __shfl_down_sync(0xffffffffu, acc.y, 20);
    float z1 = __shfl_down_sync(0xffffffffu, acc.z, 10);
    float z2 = __shfl_down_sync(0xffffffffu, acc.z, 20);
    float w1 = __shfl_down_sync(0xffffffffu, acc.w, 10);
    float w2 = __shfl_down_sync(0xffffffffu, acc.w, 20);
    if (lane < 10) {
        int fo = lane << 2;
        float4 bb = *(const float4*)&b1[fo];
        float4 r;
        r.x = acc.x + x1 + x2 + bb.x;
        r.y = acc.y + y1 + y2 + bb.y;
        r.z = acc.z + z1 + z2 + bb.z;
        r.w = acc.w + w1 + w2 + bb.w;
        *(float4*)&out[n * 40 + fo] = r;
    }
}

// ---------------- launcher ----------------
extern "C" void kernel_launch(void* const* d_in, const int* in_sizes, int n_in,
                              void* d_out, int out_size) {
    const float* x     = (const float*)d_in[0];
    const void*  ei    = d_in[1];                  // int32 or int64 — detected on device
    const float* W0    = (const float*)d_in[2];
    const float* av_s0 = (const float*)d_in[3];
    const float* av_d0 = (const float*)d_in[4];
    const float* b0    = (const float*)d_in[5];
    const float* W1    = (const float*)d_in[6];
    const float* av_s1 = (const float*)d_in[7];
    const float* av_d1 = (const float*)d_in[8];
    const float* b1    = (const float*)d_in[9];
    float* out = (float*)d_out;

    const int TB = 256;

    // ---- CSR build (shared by both layers) ----
    init_kernel<<<NBLK, TB>>>((const long long*)ei);
    hist_kernel<<<NE / TB, TB>>>(ei);
    scan1_kernel<<<NBLK, TB>>>();
    scan23_kernel<<<NBLK, TB>>>();
    scatter_kernel<<<NE / TB, TB>>>(ei);

    // ---- layer 0 ----
    gemm0_wmma_kernel<<<(NN + 63) / 64, 128>>>(x, W0, av_s0, av_d0);
    node_l0_kernel<<<(NN + 7) / 8, 256>>>(b0);

    // ---- layer 1 ----
    gemm1_kernel<<<NN / 40, 160>>>(W1);
    alpha1_kernel<<<(NN + TB - 1) / TB, TB>>>(av_s1, av_d1);
    node_l1_kernel<<<(NN + 7) / 8, 256>>>(out, b1);
}

// round 11
// speedup vs baseline: 1.3143x; 1.0127x over previous
#include <cuda_runtime.h>
#include <cuda_fp16.h>
#include <mma.h>
using namespace nvcuda;

#define NN 50000
#define NE 800000
#define NBLK ((NN + 255) / 256)   // 196 scan blocks

// ---------------- scratch (static device globals — no allocation) ----------------
__device__ __half g_h0h[NN * 128];   // layer0 features h = x@W0 (fp16 for gather)
__device__ float  g_as0[NN * 8];     // per (node, head) src projection
__device__ float  g_ad0[NN * 8];
__device__ float  g_acc0[NN * 128];  // layer0 output (post-ELU), fp32
__device__ __half g_h1h[NN * 40];    // layer1 features (fp16 for gather)
__device__ float  g_as1[NN];
__device__ float  g_ad1[NN];
__device__ int    g_csrc[NE];        // src sorted by dst (CSR payload)
__device__ int    g_cnt[NN];         // degree
__device__ int    g_off[NN];         // CSR row offsets
__device__ int    g_cur[NN];         // scatter cursors
__device__ int    g_bsum[256];
__device__ int    g_is64;

// ---------------- init: zero counters + dtype probe (fused) ----------------
__global__ void init_kernel(const long long* __restrict__ p) {
    int i = blockIdx.x * blockDim.x + threadIdx.x;
    if (i < NN) { g_cnt[i] = 0; g_cur[i] = 0; }
    if (blockIdx.x == 0) {
        __shared__ int bad;
        if (threadIdx.x == 0) bad = 0;
        __syncthreads();
        long long v = p[threadIdx.x];
        if (v < 0 || v >= NN) atomicOr(&bad, 1);
        __syncthreads();
        if (threadIdx.x == 0) g_is64 = bad ? 0 : 1;
    }
}

// histogram of dst (reads only the dst half of edge_index)
__global__ void hist_kernel(const void* __restrict__ ei) {
    int e = blockIdx.x * blockDim.x + threadIdx.x;   // exactly NE threads
    int d;
    if (g_is64) d = (int)((const long long*)ei)[NE + e];
    else        d = ((const int*)ei)[NE + e];
    atomicAdd(&g_cnt[d], 1);
}

// ---------------- block scan (2 kernels) ----------------

__global__ void scan1_kernel() {
    __shared__ int sm[256];
    int i = blockIdx.x * 256 + threadIdx.x;
    sm[threadIdx.x] = (i < NN) ? g_cnt[i] : 0;
    __syncthreads();
    for (int o = 128; o > 0; o >>= 1) {
        if (threadIdx.x < o) sm[threadIdx.x] += sm[threadIdx.x + o];
        __syncthreads();
    }
    if (threadIdx.x == 0) g_bsum[blockIdx.x] = sm[0];
}

// fused: each block computes its own prefix over g_bsum, then in-block scan
__global__ void scan23_kernel() {
    __shared__ int sm[256];
    __shared__ int boff;
    int t = threadIdx.x;
    int partial = 0;
    for (int i = t; i < blockIdx.x; i += 256) partial += g_bsum[i];
    sm[t] = partial; __syncthreads();
    for (int o = 128; o > 0; o >>= 1) {
        if (t < o) sm[t] += sm[t + o];
        __syncthreads();
    }
    if (t == 0) boff = sm[0];
    __syncthreads();
    int i = blockIdx.x * 256 + t;
    int v = (i < NN) ? g_cnt[i] : 0;
    sm[t] = v; __syncthreads();
    for (int o = 1; o < 256; o <<= 1) {
        int a = (t >= o) ? sm[t - o] : 0;
        __syncthreads();
        sm[t] += a;
        __syncthreads();
    }
    if (i < NN) g_off[i] = sm[t] - v + boff;
}

// scatter reads edge_index directly
__global__ void scatter_kernel(const void* __restrict__ ei) {
    int e = blockIdx.x * blockDim.x + threadIdx.x;   // exactly NE threads
    int s, d;
    if (g_is64) {
        const long long* p = (const long long*)ei;
        s = (int)p[e]; d = (int)p[NE + e];
    } else {
        const int* p = (const int*)ei;
        s = p[e]; d = p[NE + e];
    }
    int pos = g_off[d] + atomicAdd(&g_cur[d], 1);
    g_csrc[pos] = s;
}

// ---------------- GEMMs ----------------

// h0 = x @ W0 via fp16 WMMA (fp32 accumulate). 64 nodes/block, 4 warps.
// h0 stored fp16 (half2); alpha0 projections from the fp32 C tile.
__global__ void gemm0_wmma_kernel(const float* __restrict__ x, const float* __restrict__ W,
                                  const float* __restrict__ a_s, const float* __restrict__ a_d) {
    __shared__ __align__(16) char buf[49152];
    half*  xs = (half*)buf;                  // 64*128 half = 16KB
    half*  ws = (half*)(buf + 16384);        // 128*128 half = 32KB
    float* cs = (float*)buf;                 // 64*128 float = 32KB (aliases, post-sync)

    const int t    = threadIdx.x;            // 128
    const int warp = t >> 5;
    const int n0   = blockIdx.x * 64;

    for (int i = t; i < 64 * 128; i += 128) {
        int n = n0 + (i >> 7);
        xs[i] = __float2half(n < NN ? x[n * 128 + (i & 127)] : 0.f);
    }
    for (int i = t; i < 128 * 128; i += 128) ws[i] = __float2half(W[i]);
    __syncthreads();

    wmma::fragment<wmma::accumulator, 16, 16, 16, float> c[8];
#pragma unroll
    for (int n = 0; n < 8; n++) wmma::fill_fragment(c[n], 0.f);
#pragma unroll
    for (int k = 0; k < 8; k++) {
        wmma::fragment<wmma::matrix_a, 16, 16, 16, half, wmma::row_major> a;
        wmma::load_matrix_sync(a, xs + warp * 16 * 128 + k * 16, 128);
#pragma unroll
        for (int n = 0; n < 8; n++) {
            wmma::fragment<wmma::matrix_b, 16, 16, 16, half, wmma::row_major> b;
            wmma::load_matrix_sync(b, ws + k * 16 * 128 + n * 16, 128);
            wmma::mma_sync(c[n], a, b, c[n]);
        }
    }
    __syncthreads();   // done reading xs/ws; cs may now overwrite them
#pragma unroll
    for (int n = 0; n < 8; n++)
        wmma::store_matrix_sync(cs + warp * 16 * 128 + n * 16, c[n], 128, wmma::mem_row_major);
    __syncthreads();

    // write h0 as fp16 (half2 pairs; rows are 128 wide so pairs never cross rows)
    for (int i = t; i < 64 * 64; i += 128) {       // i indexes half2 pairs
        int el = i * 2;
        int n = n0 + (el >> 7);
        if (n < NN)
            *(__half2*)&g_h0h[n * 128 + (el & 127)] =
                __floats2half2_rn(cs[el], cs[el + 1]);
    }
    // alpha projections: 512 (row, head) pairs, 4 per thread
    for (int p = t; p < 512; p += 128) {
        int r = p >> 3, h = p & 7;
        int n = n0 + r;
        if (n < NN) {
            const float* cp = cs + r * 128 + h * 16;
            float s = 0.f, d = 0.f;
#pragma unroll
            for (int j = 0; j < 16; j++) {
                float v = cp[j];
                s += v * a_s[h * 16 + j];
                d += v * a_d[h * 16 + j];
            }
            g_as0[n * 8 + h] = s;
            g_ad0[n * 8 + h] = d;
        }
    }
}

// h1 = elu_out @ W1 (50000x128 @ 128x40). 40 nodes/block, 160 threads. fp16 out.
__global__ void gemm1_kernel(const float* __restrict__ W1) {
    __shared__ float xs[40 * 128];
    __shared__ float ws[128 * 40];
    const int t  = threadIdx.x;
    const int n0 = blockIdx.x * 40;
    for (int i = t; i < 40 * 128; i += 160) xs[i] = g_acc0[n0 * 128 + i];
    for (int i = t; i < 128 * 40; i += 160) ws[i] = W1[i];
    __syncthreads();
    const int c = t % 40, ns = t / 40;
    float acc[10];
#pragma unroll
    for (int j = 0; j < 10; j++) acc[j] = 0.f;
    for (int k = 0; k < 128; k += 4) {
        float w0 = ws[k * 40 + c], w1 = ws[(k + 1) * 40 + c];
        float w2 = ws[(k + 2) * 40 + c], w3 = ws[(k + 3) * 40 + c];
#pragma unroll
        for (int j = 0; j < 10; j++) {
            float4 xv = *(const float4*)&xs[(ns + 4 * j) * 128 + k];
            acc[j] += xv.x * w0 + xv.y * w1 + xv.z * w2 + xv.w * w3;
        }
    }
#pragma unroll
    for (int j = 0; j < 10; j++)
        g_h1h[(n0 + ns + 4 * j) * 40 + c] = __float2half(acc[j]);
}

__global__ void alpha1_kernel(const float* __restrict__ a_s, const float* __restrict__ a_d) {
    int n = blockIdx.x * blockDim.x + threadIdx.x;
    if (n >= NN) return;
    const __half2* hp = (const __half2*)&g_h1h[n * 40];
    float s = 0.f, d = 0.f;
#pragma unroll
    for (int j = 0; j < 20; j++) {
        float2 v = __half22float2(hp[j]);
        s += v.x * a_s[2 * j] + v.y * a_s[2 * j + 1];
        d += v.x * a_d[2 * j] + v.y * a_d[2 * j + 1];
    }
    g_as1[n] = s; g_ad1[n] = d;
}

// ---------------- fused per-node softmax + aggregation ----------------
// Softmax without max-subtraction (logits are O(1) here; identical result).

__device__ __forceinline__ float lrelu_exp(float v) {
    v = v > 0.f ? v : 0.2f * v;
    return __expf(v);
}

__device__ __forceinline__ float4 h4_to_f4(uint2 u) {
    float2 a = __half22float2(*(__half2*)&u.x);
    float2 b = __half22float2(*(__half2*)&u.y);
    return make_float4(a.x, a.y, b.x, b.y);
}

// layer0: one warp per node. 8 heads x 16 dims; h0 gathered fp16 (8B/lane).
__global__ void node_l0_kernel(const float* __restrict__ b0) {
    int n = blockIdx.x * (blockDim.x >> 5) + (threadIdx.x >> 5);
    if (n >= NN) return;
    int lane = threadIdx.x & 31;
    int off = g_off[n], deg = g_cnt[n];

    float ad[8];
#pragma unroll
    for (int h = 0; h < 8; h++) ad[h] = g_ad0[n * 8 + h];

    float den[8] = {0.f, 0.f, 0.f, 0.f, 0.f, 0.f, 0.f, 0.f};
    for (int j = lane; j < deg; j += 32) {
        int s = g_csrc[off + j];
        float4 a0 = *(const float4*)&g_as0[s * 8];
        float4 a1 = *(const float4*)&g_as0[s * 8 + 4];
        den[0] += lrelu_exp(a0.x + ad[0]);
        den[1] += lrelu_exp(a0.y + ad[1]);
        den[2] += lrelu_exp(a0.z + ad[2]);
        den[3] += lrelu_exp(a0.w + ad[3]);
        den[4] += lrelu_exp(a1.x + ad[4]);
        den[5] += lrelu_exp(a1.y + ad[5]);
        den[6] += lrelu_exp(a1.z + ad[6]);
        den[7] += lrelu_exp(a1.w + ad[7]);
    }
#pragma unroll
    for (int h = 0; h < 8; h++) {
        float v = den[h];
#pragma unroll
        for (int o = 16; o > 0; o >>= 1) v += __shfl_xor_sync(0xffffffffu, v, o);
        den[h] = 1.f / (v + 1e-16f);
    }

    int h = lane >> 2, f = lane << 2;
    float inv = (h == 0) ? den[0] : (h == 1) ? den[1] : (h == 2) ? den[2] :
                (h == 3) ? den[3] : (h == 4) ? den[4] : (h == 5) ? den[5] :
                (h == 6) ? den[6] : den[7];
    float adh = (h == 0) ? ad[0] : (h == 1) ? ad[1] : (h == 2) ? ad[2] :
                (h == 3) ? ad[3] : (h == 4) ? ad[4] : (h == 5) ? ad[5] :
                (h == 6) ? ad[6] : ad[7];

    float4 acc = make_float4(0.f, 0.f, 0.f, 0.f);
    int j = 0;
    for (; j + 4 <= deg; j += 4) {
        int s0 = g_csrc[off + j],     s1 = g_csrc[off + j + 1];
        int s2 = g_csrc[off + j + 2], s3 = g_csrc[off + j + 3];
        float q0 = g_as0[s0 * 8 + h], q1 = g_as0[s1 * 8 + h];
        float q2 = g_as0[s2 * 8 + h], q3 = g_as0[s3 * 8 + h];
        uint2 u0 = *(const uint2*)&g_h0h[s0 * 128 + f];
        uint2 u1 = *(const uint2*)&g_h0h[s1 * 128 + f];
        uint2 u2 = *(const uint2*)&g_h0h[s2 * 128 + f];
        uint2 u3 = *(const uint2*)&g_h0h[s3 * 128 + f];
        float a0 = lrelu_exp(q0 + adh) * inv;
        float a1 = lrelu_exp(q1 + adh) * inv;
        float a2 = lrelu_exp(q2 + adh) * inv;
        float a3 = lrelu_exp(q3 + adh) * inv;
        float4 v0 = h4_to_f4(u0), v1 = h4_to_f4(u1);
        float4 v2 = h4_to_f4(u2), v3 = h4_to_f4(u3);
        acc.x += v0.x * a0 + v1.x * a1 + v2.x * a2 + v3.x * a3;
        acc.y += v0.y * a0 + v1.y * a1 + v2.y * a2 + v3.y * a3;
        acc.z += v0.z * a0 + v1.z * a1 + v2.z * a2 + v3.z * a3;
        acc.w += v0.w * a0 + v1.w * a1 + v2.w * a2 + v3.w * a3;
    }
    for (; j < deg; j++) {
        int s = g_csrc[off + j];
        float a = lrelu_exp(g_as0[s * 8 + h] + adh) * inv;
        float4 hv = h4_to_f4(*(const uint2*)&g_h0h[s * 128 + f]);
        acc.x += hv.x * a; acc.y += hv.y * a;
        acc.z += hv.z * a; acc.w += hv.w * a;
    }
    float4 bb = *(const float4*)&b0[f];
    acc.x += bb.x; acc.y += bb.y; acc.z += bb.z; acc.w += bb.w;
    acc.x = acc.x > 0.f ? acc.x : expm1f(acc.x);
    acc.y = acc.y > 0.f ? acc.y : expm1f(acc.y);
    acc.z = acc.z > 0.f ? acc.z : expm1f(acc.z);
    acc.w = acc.w > 0.f ? acc.w : expm1f(acc.w);
    *(float4*)&g_acc0[n * 128 + f] = acc;
}

// layer1: one warp per node; lanes 0-29 split edges 3 ways (10 lanes x 4 feats).
__global__ void node_l1_kernel(float* __restrict__ out, const float* __restrict__ b1) {
    int n = blockIdx.x * (blockDim.x >> 5) + (threadIdx.x >> 5);
    if (n >= NN) return;
    int lane = threadIdx.x & 31;
    int off = g_off[n], deg = g_cnt[n];

    float adv = g_ad1[n];
    float den = 0.f;
    for (int j = lane; j < deg; j += 32) {
        den += lrelu_exp(g_as1[g_csrc[off + j]] + adv);
    }
#pragma unroll
    for (int o = 16; o > 0; o >>= 1) den += __shfl_xor_sync(0xffffffffu, den, o);
    float inv = 1.f / (den + 1e-16f);

    int grp = lane / 10;           // 0,1,2 active; lanes 30,31 idle
    int f   = (lane - grp * 10) << 2;
    float4 acc = make_float4(0.f, 0.f, 0.f, 0.f);
    if (grp < 3) {
        int j = grp;
        for (; j + 4 <= deg; j += 6) {       // handles edges j and j+3
            int s0 = g_csrc[off + j], s1 = g_csrc[off + j + 3];
            float q0 = g_as1[s0], q1 = g_as1[s1];
            uint2 u0 = *(const uint2*)&g_h1h[s0 * 40 + f];
            uint2 u1 = *(const uint2*)&g_h1h[s1 * 40 + f];
            float a0 = lrelu_exp(q0 + adv) * inv;
            float a1 = lrelu_exp(q1 + adv) * inv;
            float4 v0 = h4_to_f4(u0), v1 = h4_to_f4(u1);
            acc.x += v0.x * a0 + v1.x * a1;
            acc.y += v0.y * a0 + v1.y * a1;
            acc.z += v0.z * a0 + v1.z * a1;
            acc.w += v0.w * a0 + v1.w * a1;
        }
        for (; j < deg; j += 3) {
            int s = g_csrc[off + j];
            float a = lrelu_exp(g_as1[s] + adv) * inv;
            float4 hv = h4_to_f4(*(const uint2*)&g_h1h[s * 40 + f]);
            acc.x += hv.x * a; acc.y += hv.y * a;
            acc.z += hv.z * a; acc.w += hv.w * a;
        }
    }
    // combine the 3 group partials into lanes 0..9
    float x1 = __shfl_down_sync(0xffffffffu, acc.x, 10);
    float x2 = __shfl_down_sync(0xffffffffu, acc.x, 20);
    float y1 = __shfl_down_sync(0xffffffffu, acc.y, 10);
    float y2 = __shfl_down_sync(0xffffffffu, acc.y, 20);
    float z1 = __shfl_down_sync(0xffffffffu, acc.z, 10);
    float z2 = __shfl_down_sync(0xffffffffu, acc.z, 20);
    float w1 = __shfl_down_sync(0xffffffffu, acc.w, 10);
    float w2 = __shfl_down_sync(0xffffffffu, acc.w, 20);
    if (lane < 10) {
        int fo = lane << 2;
        float4 bb = *(const float4*)&b1[fo];
        float4 r;
        r.x = acc.x + x1 + x2 + bb.x;
        r.y = acc.y + y1 + y2 + bb.y;
        r.z = acc.z + z1 + z2 + bb.z;
        r.w = acc.w + w1 + w2 + bb.w;
        *(float4*)&out[n * 40 + fo] = r;
    }
}

// ---------------- launcher ----------------
extern "C" void kernel_launch(void* const* d_in, const int* in_sizes, int n_in,
                              void* d_out, int out_size) {
    const float* x     = (const float*)d_in[0];
    const void*  ei    = d_in[1];                  // int32 or int64 — detected on device
    const float* W0    = (const float*)d_in[2];
    const float* av_s0 = (const float*)d_in[3];
    const float* av_d0 = (const float*)d_in[4];
    const float* b0    = (const float*)d_in[5];
    const float* W1    = (const float*)d_in[6];
    const float* av_s1 = (const float*)d_in[7];
    const float* av_d1 = (const float*)d_in[8];
    const float* b1    = (const float*)d_in[9];
    float* out = (float*)d_out;

    const int TB = 256;

    // ---- CSR build (shared by both layers) ----
    init_kernel<<<NBLK, TB>>>((const long long*)ei);
    hist_kernel<<<NE / TB, TB>>>(ei);
    scan1_kernel<<<NBLK, TB>>>();
    scan23_kernel<<<NBLK, TB>>>();
    scatter_kernel<<<NE / TB, TB>>>(ei);

    // ---- layer 0 ----
    gemm0_wmma_kernel<<<(NN + 63) / 64, 128>>>(x, W0, av_s0, av_d0);
    node_l0_kernel<<<(NN + 7) / 8, 256>>>(b0);

    // ---- layer 1 ----
    gemm1_kernel<<<NN / 40, 160>>>(W1);
    alpha1_kernel<<<(NN + TB - 1) / TB, TB>>>(av_s1, av_d1);
    node_l1_kernel<<<(NN + 7) / 8, 256>>>(out, b1);
}

// round 12
// speedup vs baseline: 1.4328x; 1.0901x over previous
#include <cuda_runtime.h>
#include <cuda_fp16.h>
#include <mma.h>
using namespace nvcuda;

#define NN 50000
#define NE 800000
#define NBLK ((NN + 255) / 256)   // 196 scan blocks

// ---------------- scratch (static device globals — no allocation) ----------------
__device__ __half g_h0h[NN * 128];   // layer0 features h = x@W0 (fp16 for gather)
__device__ float  g_as0[NN * 8];     // per (node, head) src projection
__device__ float  g_ad0[NN * 8];
__device__ float  g_acc0[NN * 128];  // layer0 output (post-ELU), fp32
__device__ __half g_h1h[NN * 40];    // layer1 features (fp16 for gather)
__device__ float  g_as1[NN];
__device__ float  g_ad1[NN];
__device__ int    g_csrc[NE];        // src sorted by dst (CSR payload)
__device__ int    g_cnt[NN];         // degree
__device__ int    g_off[NN];         // CSR row offsets
__device__ int    g_cur[NN];         // scatter cursors (pre-seeded with g_off)
__device__ int    g_is64;

// ---------------- init: zero counters + dtype probe (fused) ----------------
__global__ void init_kernel(const long long* __restrict__ p) {
    int i = blockIdx.x * blockDim.x + threadIdx.x;
    if (i < NN) g_cnt[i] = 0;
    if (blockIdx.x == 0) {
        __shared__ int bad;
        if (threadIdx.x == 0) bad = 0;
        __syncthreads();
        long long v = p[threadIdx.x];
        if (v < 0 || v >= NN) atomicOr(&bad, 1);
        __syncthreads();
        if (threadIdx.x == 0) g_is64 = bad ? 0 : 1;
    }
}

// histogram of dst (reads only the dst half of edge_index)
__global__ void hist_kernel(const void* __restrict__ ei) {
    int e = blockIdx.x * blockDim.x + threadIdx.x;   // exactly NE threads
    int d;
    if (g_is64) d = (int)((const long long*)ei)[NE + e];
    else        d = ((const int*)ei)[NE + e];
    atomicAdd(&g_cnt[d], 1);
}

// ---------------- single-kernel exclusive scan ----------------
// Block b: sum g_cnt[0 .. 256b) directly (19.6MB total L2 reads across blocks),
// then in-block inclusive scan. Also seeds g_cur with the offsets.
__global__ void scan_kernel() {
    __shared__ int sm[256];
    __shared__ int boff;
    int t = threadIdx.x;
    int lim = blockIdx.x * 256;
    int partial = 0;
    for (int i = t; i < lim; i += 256) partial += g_cnt[i];
    sm[t] = partial; __syncthreads();
    for (int o = 128; o > 0; o >>= 1) {
        if (t < o) sm[t] += sm[t + o];
        __syncthreads();
    }
    if (t == 0) boff = sm[0];
    __syncthreads();
    int i = lim + t;
    int v = (i < NN) ? g_cnt[i] : 0;
    sm[t] = v; __syncthreads();
    for (int o = 1; o < 256; o <<= 1) {
        int a = (t >= o) ? sm[t - o] : 0;
        __syncthreads();
        sm[t] += a;
        __syncthreads();
    }
    if (i < NN) {
        int off = sm[t] - v + boff;
        g_off[i] = off;
        g_cur[i] = off;
    }
}

// scatter: atomic on pre-seeded cursor gives the CSR slot directly
__global__ void scatter_kernel(const void* __restrict__ ei) {
    int e = blockIdx.x * blockDim.x + threadIdx.x;   // exactly NE threads
    int s, d;
    if (g_is64) {
        const long long* p = (const long long*)ei;
        s = (int)p[e]; d = (int)p[NE + e];
    } else {
        const int* p = (const int*)ei;
        s = p[e]; d = p[NE + e];
    }
    g_csrc[atomicAdd(&g_cur[d], 1)] = s;
}

// ---------------- GEMMs ----------------

// h0 = x @ W0 via fp16 WMMA (fp32 accumulate). 64 nodes/block, 4 warps.
__global__ void gemm0_wmma_kernel(const float* __restrict__ x, const float* __restrict__ W,
                                  const float* __restrict__ a_s, const float* __restrict__ a_d) {
    __shared__ __align__(16) char buf[49152];
    half*  xs = (half*)buf;                  // 64*128 half = 16KB
    half*  ws = (half*)(buf + 16384);        // 128*128 half = 32KB
    float* cs = (float*)buf;                 // 64*128 float = 32KB (aliases, post-sync)

    const int t    = threadIdx.x;            // 128
    const int warp = t >> 5;
    const int n0   = blockIdx.x * 64;

    for (int i = t; i < 64 * 128; i += 128) {
        int n = n0 + (i >> 7);
        xs[i] = __float2half(n < NN ? x[n * 128 + (i & 127)] : 0.f);
    }
    for (int i = t; i < 128 * 128; i += 128) ws[i] = __float2half(W[i]);
    __syncthreads();

    wmma::fragment<wmma::accumulator, 16, 16, 16, float> c[8];
#pragma unroll
    for (int n = 0; n < 8; n++) wmma::fill_fragment(c[n], 0.f);
#pragma unroll
    for (int k = 0; k < 8; k++) {
        wmma::fragment<wmma::matrix_a, 16, 16, 16, half, wmma::row_major> a;
        wmma::load_matrix_sync(a, xs + warp * 16 * 128 + k * 16, 128);
#pragma unroll
        for (int n = 0; n < 8; n++) {
            wmma::fragment<wmma::matrix_b, 16, 16, 16, half, wmma::row_major> b;
            wmma::load_matrix_sync(b, ws + k * 16 * 128 + n * 16, 128);
            wmma::mma_sync(c[n], a, b, c[n]);
        }
    }
    __syncthreads();
#pragma unroll
    for (int n = 0; n < 8; n++)
        wmma::store_matrix_sync(cs + warp * 16 * 128 + n * 16, c[n], 128, wmma::mem_row_major);
    __syncthreads();

    // write h0 as fp16 half2 pairs
    for (int i = t; i < 64 * 64; i += 128) {
        int el = i * 2;
        int n = n0 + (el >> 7);
        if (n < NN)
            *(__half2*)&g_h0h[n * 128 + (el & 127)] =
                __floats2half2_rn(cs[el], cs[el + 1]);
    }
    // alpha projections: 512 (row, head) pairs
    for (int p = t; p < 512; p += 128) {
        int r = p >> 3, h = p & 7;
        int n = n0 + r;
        if (n < NN) {
            const float* cp = cs + r * 128 + h * 16;
            float s = 0.f, d = 0.f;
#pragma unroll
            for (int j = 0; j < 16; j++) {
                float v = cp[j];
                s += v * a_s[h * 16 + j];
                d += v * a_d[h * 16 + j];
            }
            g_as0[n * 8 + h] = s;
            g_ad0[n * 8 + h] = d;
        }
    }
}

// h1 = elu_out @ W1 (50000x128 @ 128x40). 40 nodes/block, 160 threads. fp16 out.
__global__ void gemm1_kernel(const float* __restrict__ W1) {
    __shared__ float xs[40 * 128];
    __shared__ float ws[128 * 40];
    const int t  = threadIdx.x;
    const int n0 = blockIdx.x * 40;
    for (int i = t; i < 40 * 128; i += 160) xs[i] = g_acc0[n0 * 128 + i];
    for (int i = t; i < 128 * 40; i += 160) ws[i] = W1[i];
    __syncthreads();
    const int c = t % 40, ns = t / 40;
    float acc[10];
#pragma unroll
    for (int j = 0; j < 10; j++) acc[j] = 0.f;
    for (int k = 0; k < 128; k += 4) {
        float w0 = ws[k * 40 + c], w1 = ws[(k + 1) * 40 + c];
        float w2 = ws[(k + 2) * 40 + c], w3 = ws[(k + 3) * 40 + c];
#pragma unroll
        for (int j = 0; j < 10; j++) {
            float4 xv = *(const float4*)&xs[(ns + 4 * j) * 128 + k];
            acc[j] += xv.x * w0 + xv.y * w1 + xv.z * w2 + xv.w * w3;
        }
    }
#pragma unroll
    for (int j = 0; j < 10; j++)
        g_h1h[(n0 + ns + 4 * j) * 40 + c] = __float2half(acc[j]);
}

__global__ void alpha1_kernel(const float* __restrict__ a_s, const float* __restrict__ a_d) {
    int n = blockIdx.x * blockDim.x + threadIdx.x;
    if (n >= NN) return;
    const __half2* hp = (const __half2*)&g_h1h[n * 40];
    float s = 0.f, d = 0.f;
#pragma unroll
    for (int j = 0; j < 20; j++) {
        float2 v = __half22float2(hp[j]);
        s += v.x * a_s[2 * j] + v.y * a_s[2 * j + 1];
        d += v.x * a_d[2 * j] + v.y * a_d[2 * j + 1];
    }
    g_as1[n] = s; g_ad1[n] = d;
}

// ---------------- single-pass fused softmax + aggregation ----------------
// out = (Σ ex_i h_i) / (Σ ex_i): numerator and denominator accumulate in ONE
// edge loop; normalize once at the end. No max-subtraction (logits O(1) here).

__device__ __forceinline__ float lrelu_exp(float v) {
    v = v > 0.f ? v : 0.2f * v;
    return __expf(v);
}

__device__ __forceinline__ float4 h4_to_f4(uint2 u) {
    float2 a = __half22float2(*(__half2*)&u.x);
    float2 b = __half22float2(*(__half2*)&u.y);
    return make_float4(a.x, a.y, b.x, b.y);
}

// layer0: one warp per node; lane covers 4 features of head lane/4.
// Every lane walks ALL edges, so its private den is already the full sum.
__global__ void node_l0_kernel(const float* __restrict__ b0) {
    int n = blockIdx.x * (blockDim.x >> 5) + (threadIdx.x >> 5);
    if (n >= NN) return;
    int lane = threadIdx.x & 31;
    int off = g_off[n], deg = g_cnt[n];
    int h = lane >> 2, f = lane << 2;
    float adh = g_ad0[n * 8 + h];

    float den = 0.f;
    float4 acc = make_float4(0.f, 0.f, 0.f, 0.f);
    int j = 0;
    for (; j + 4 <= deg; j += 4) {
        int s0 = g_csrc[off + j],     s1 = g_csrc[off + j + 1];
        int s2 = g_csrc[off + j + 2], s3 = g_csrc[off + j + 3];
        float q0 = g_as0[s0 * 8 + h], q1 = g_as0[s1 * 8 + h];
        float q2 = g_as0[s2 * 8 + h], q3 = g_as0[s3 * 8 + h];
        uint2 u0 = *(const uint2*)&g_h0h[s0 * 128 + f];
        uint2 u1 = *(const uint2*)&g_h0h[s1 * 128 + f];
        uint2 u2 = *(const uint2*)&g_h0h[s2 * 128 + f];
        uint2 u3 = *(const uint2*)&g_h0h[s3 * 128 + f];
        float a0 = lrelu_exp(q0 + adh), a1 = lrelu_exp(q1 + adh);
        float a2 = lrelu_exp(q2 + adh), a3 = lrelu_exp(q3 + adh);
        den += (a0 + a1) + (a2 + a3);
        float4 v0 = h4_to_f4(u0), v1 = h4_to_f4(u1);
        float4 v2 = h4_to_f4(u2), v3 = h4_to_f4(u3);
        acc.x += v0.x * a0 + v1.x * a1 + v2.x * a2 + v3.x * a3;
        acc.y += v0.y * a0 + v1.y * a1 + v2.y * a2 + v3.y * a3;
        acc.z += v0.z * a0 + v1.z * a1 + v2.z * a2 + v3.z * a3;
        acc.w += v0.w * a0 + v1.w * a1 + v2.w * a2 + v3.w * a3;
    }
    for (; j < deg; j++) {
        int s = g_csrc[off + j];
        float a = lrelu_exp(g_as0[s * 8 + h] + adh);
        float4 hv = h4_to_f4(*(const uint2*)&g_h0h[s * 128 + f]);
        den += a;
        acc.x += hv.x * a; acc.y += hv.y * a;
        acc.z += hv.z * a; acc.w += hv.w * a;
    }
    float inv = 1.f / (den + 1e-16f);
    float4 bb = *(const float4*)&b0[f];
    acc.x = acc.x * inv + bb.x;
    acc.y = acc.y * inv + bb.y;
    acc.z = acc.z * inv + bb.z;
    acc.w = acc.w * inv + bb.w;
    acc.x = acc.x > 0.f ? acc.x : expm1f(acc.x);
    acc.y = acc.y > 0.f ? acc.y : expm1f(acc.y);
    acc.z = acc.z > 0.f ? acc.z : expm1f(acc.z);
    acc.w = acc.w > 0.f ? acc.w : expm1f(acc.w);
    *(float4*)&g_acc0[n * 128 + f] = acc;
}

// layer1: one warp per node; lanes 0-29 in 3 groups of 10 split the edges.
// Each group accumulates partial numerator AND denominator; shuffle-combined.
__global__ void node_l1_kernel(float* __restrict__ out, const float* __restrict__ b1) {
    int n = blockIdx.x * (blockDim.x >> 5) + (threadIdx.x >> 5);
    if (n >= NN) return;
    int lane = threadIdx.x & 31;
    int off = g_off[n], deg = g_cnt[n];
    float adv = g_ad1[n];

    int grp = lane / 10;           // 0,1,2 active; lanes 30,31 idle
    int f   = (lane - grp * 10) << 2;
    float den = 0.f;
    float4 acc = make_float4(0.f, 0.f, 0.f, 0.f);
    if (grp < 3) {
        int j = grp;
        for (; j + 4 <= deg; j += 6) {       // edges j and j+3
            int s0 = g_csrc[off + j], s1 = g_csrc[off + j + 3];
            float q0 = g_as1[s0], q1 = g_as1[s1];
            uint2 u0 = *(const uint2*)&g_h1h[s0 * 40 + f];
            uint2 u1 = *(const uint2*)&g_h1h[s1 * 40 + f];
            float a0 = lrelu_exp(q0 + adv);
            float a1 = lrelu_exp(q1 + adv);
            den += a0 + a1;
            float4 v0 = h4_to_f4(u0), v1 = h4_to_f4(u1);
            acc.x += v0.x * a0 + v1.x * a1;
            acc.y += v0.y * a0 + v1.y * a1;
            acc.z += v0.z * a0 + v1.z * a1;
            acc.w += v0.w * a0 + v1.w * a1;
        }
        for (; j < deg; j += 3) {
            int s = g_csrc[off + j];
            float a = lrelu_exp(g_as1[s] + adv);
            float4 hv = h4_to_f4(*(const uint2*)&g_h1h[s * 40 + f]);
            den += a;
            acc.x += hv.x * a; acc.y += hv.y * a;
            acc.z += hv.z * a; acc.w += hv.w * a;
        }
    }
    // combine the 3 group partials into lanes 0..9
    float d1 = __shfl_down_sync(0xffffffffu, den, 10);
    float d2 = __shfl_down_sync(0xffffffffu, den, 20);
    float x1 = __shfl_down_sync(0xffffffffu, acc.x, 10);
    float x2 = __shfl_down_sync(0xffffffffu, acc.x, 20);
    float y1 = __shfl_down_sync(0xffffffffu, acc.y, 10);
    float y2 = __shfl_down_sync(0xffffffffu, acc.y, 20);
    float z1 = __shfl_down_sync(0xffffffffu, acc.z, 10);
    float z2 = __shfl_down_sync(0xffffffffu, acc.z, 20);
    float w1 = __shfl_down_sync(0xffffffffu, acc.w, 10);
    float w2 = __shfl_down_sync(0xffffffffu, acc.w, 20);
    if (lane < 10) {
        float inv = 1.f / ((den + d1 + d2) + 1e-16f);
        int fo = lane << 2;
        float4 bb = *(const float4*)&b1[fo];
        float4 r;
        r.x = (acc.x + x1 + x2) * inv + bb.x;
        r.y = (acc.y + y1 + y2) * inv + bb.y;
        r.z = (acc.z + z1 + z2) * inv + bb.z;
        r.w = (acc.w + w1 + w2) * inv + bb.w;
        *(float4*)&out[n * 40 + fo] = r;
    }
}

// ---------------- launcher ----------------
extern "C" void kernel_launch(void* const* d_in, const int* in_sizes, int n_in,
                              void* d_out, int out_size) {
    const float* x     = (const float*)d_in[0];
    const void*  ei    = d_in[1];                  // int32 or int64 — detected on device
    const float* W0    = (const float*)d_in[2];
    const float* av_s0 = (const float*)d_in[3];
    const float* av_d0 = (const float*)d_in[4];
    const float* b0    = (const float*)d_in[5];
    const float* W1    = (const float*)d_in[6];
    const float* av_s1 = (const float*)d_in[7];
    const float* av_d1 = (const float*)d_in[8];
    const float* b1    = (const float*)d_in[9];
    float* out = (float*)d_out;

    const int TB = 256;

    // ---- CSR build (shared by both layers) ----
    init_kernel<<<NBLK, TB>>>((const long long*)ei);
    hist_kernel<<<NE / TB, TB>>>(ei);
    scan_kernel<<<NBLK, TB>>>();
    scatter_kernel<<<NE / TB, TB>>>(ei);

    // ---- layer 0 ----
    gemm0_wmma_kernel<<<(NN + 63) / 64, 128>>>(x, W0, av_s0, av_d0);
    node_l0_kernel<<<(NN + 7) / 8, 256>>>(b0);

    // ---- layer 1 ----
    gemm1_kernel<<<NN / 40, 160>>>(W1);
    alpha1_kernel<<<(NN + TB - 1) / TB, TB>>>(av_s1, av_d1);
    node_l1_kernel<<<(NN + 7) / 8, 256>>>(out, b1);
}